// round 14
// baseline (speedup 1.0000x reference)
#include <cuda_runtime.h>
#include <cstdint>

// R14: A/B probe — default write-back stores instead of __stcs.
// Everything else identical to the 26.656 us best (R8/R13 config).

#define BB 8
#define SS 8192
#define NTOK (BB * SS)
#define TOKC 2048
#define NCH (NTOK / TOKC)      // 32 token chunks
#define SLICES 16

typedef unsigned long long u64;
typedef unsigned int u32;
typedef unsigned short u16;

// dynamic smem layout (bytes):
//   [0,      34816)  float4 stbl[272*8]   table slice (32 dims)
//   [34816,  38912)  u16   stok[2048]     chunk tokens
//   [38912,  47104)  u32   smask[2048]    per-token mask slice (sl 6/7 only)
//   [47104,  47168)  int   warp_part[16]
//   [47168,  47232)  int   warp_min[16]
//   [47232,  47236)  int   s_fce
#define SMEM_BYTES 47296

__global__ void __launch_bounds__(512, 3) nvm_fused_kernel(
    const float4* __restrict__ tbl4,     // [272 * 128]
    const int*    __restrict__ tok,      // [NTOK]
    float4*       __restrict__ out4)     // [NTOK * 128]
{
    extern __shared__ char smem[];
    float4* stbl      = (float4*)(smem);
    u16*    stok      = (u16*)(smem + 34816);
    u32*    smask     = (u32*)(smem + 38912);
    int*    warp_part = (int*)(smem + 47104);
    int*    warp_min  = (int*)(smem + 47168);
    int*    s_fce     = (int*)(smem + 47232);

    int sl      = blockIdx.y;            // 0..15 dim slice
    int tokbase = blockIdx.x * TOKC;
    int b       = tokbase >> 13;         // batch row
    int ci      = (tokbase >> 11) & 3;   // chunk within row (0..3)
    int tid     = threadIdx.x;
    int lane    = tid & 31, wid = tid >> 5;

    // ---- stage table slice (272 rows x 8 float4) ----
#pragma unroll
    for (int i = tid; i < 272 * 8; i += 512)
        stbl[i] = __ldg(&tbl4[(i >> 3) * 128 + sl * 8 + (i & 7)]);

    // ---- stage chunk tokens as u16 ----
    {
        const int4* tok4 = (const int4*)(tok + tokbase);
        u32* st32 = (u32*)stok;
#pragma unroll
        for (int i = tid; i < TOKC / 4; i += 512) {
            int4 v = __ldg(&tok4[i]);
            st32[2 * i]     = (u32)v.x | ((u32)v.y << 16);
            st32[2 * i + 1] = (u32)v.z | ((u32)v.w << 16);
        }
    }

    // ---- slices 6/7: full-row scan + mask build into smem ----
    if (sl == 6 || sl == 7) {
        const int4* row4 = (const int4*)(tok + b * SS);
        int base = tid * 16;                 // row-relative start

        int own[16];
        {
            int4 v0 = __ldg(&row4[tid * 4 + 0]);
            int4 v1 = __ldg(&row4[tid * 4 + 1]);
            int4 v2 = __ldg(&row4[tid * 4 + 2]);
            int4 v3 = __ldg(&row4[tid * 4 + 3]);
            own[0]=v0.x; own[1]=v0.y; own[2]=v0.z; own[3]=v0.w;
            own[4]=v1.x; own[5]=v1.y; own[6]=v1.z; own[7]=v1.w;
            own[8]=v2.x; own[9]=v2.y; own[10]=v2.z; own[11]=v2.w;
            own[12]=v3.x; own[13]=v3.y; own[14]=v3.z; own[15]=v3.w;
        }

        int run = -1, lce = SS;
#pragma unroll
        for (int i = 0; i < 16; i++) {
            int t = own[i];
            if (t == 256) run = base + i;
            if (t == 257 && (base + i) < lce) lce = base + i;
        }
        int e = lce;
#pragma unroll
        for (int off = 16; off > 0; off >>= 1) {
            int o = __shfl_down_sync(0xffffffffu, e, off);
            if (o < e) e = o;
        }
        int v = run;
#pragma unroll
        for (int off = 1; off < 32; off <<= 1) {
            int o = __shfl_up_sync(0xffffffffu, v, off);
            if (lane >= off && o > v) v = o;
        }
        if (lane == 0)  warp_min[wid]  = e;
        if (lane == 31) warp_part[wid] = v;
        __syncthreads();
        if (wid == 0 && lane < 16) {
            int w = warp_part[lane];
#pragma unroll
            for (int off = 1; off < 16; off <<= 1) {
                int o = __shfl_up_sync(0x0000ffffu, w, off);
                if (lane >= off && o > w) w = o;
            }
            warp_part[lane] = w;
            if (lane == 0) {
                int f = SS;
#pragma unroll
                for (int i = 0; i < 16; i++)
                    if (warp_min[i] < f) f = warp_min[i];
                *s_fce = f;
            }
        }
        __syncthreads();

        int wpre = (wid == 0) ? -1 : warp_part[wid - 1];
        int excl = __shfl_up_sync(0xffffffffu, v, 1);
        if (lane == 0) excl = -1;
        int prefix = (excl > wpre) ? excl : wpre;
        int fce = *s_fce;

        // only threads whose 16 tokens lie in this block's chunk build masks
        if ((tid >> 7) == ci) {
            int h[8];
#pragma unroll
            for (int j = 0; j < 8; j++) h[j] = -1;
            if (tid > 0) {
                int4 ha = __ldg(&row4[tid * 4 - 2]);
                int4 hb = __ldg(&row4[tid * 4 - 1]);
                h[0]=ha.x; h[1]=ha.y; h[2]=ha.z; h[3]=ha.w;
                h[4]=hb.x; h[5]=hb.y; h[6]=hb.z; h[7]=hb.w;
            }
            int cur = prefix;
            int shift = (sl == 6) ? 0 : 18;
            int mbase = base - ci * TOKC;        // chunk-relative
#pragma unroll
            for (int i = 0; i < 16; i++) {
                int s = base + i;
                int t = own[i];
                if (t == 256) cur = s;           // inclusive cummax
                u64 m = 0ull;
                // code path
                if (cur >= 0 && s < fce && t < 256) {
                    int seq = s - cur - 1;
                    int bo  = seq & 7;
                    if (seq >= 0 && bo < 5) {
                        int addr = ((seq & ~7) + 2 + bo) & 4095;
                        m |= (1ull << (addr & 15))
                           | (1ull << (16 + ((addr >> 4) & 15)))
                           | (1ull << (32 + ((addr >> 8) & 15)));
                    }
                }
                // mem look-back: j = s-5-off, window idx wi = i-5-off in [-8,10]
#pragma unroll
                for (int off = 0; off < 4; off++) {
                    int jg = s - 5 - off;
                    if (jg >= 0 && (jg + 8) < SS) {
                        const int wi = i - 5 - off;
                        int tj  = (wi   >= 0) ? own[wi]     : h[wi + 8];
                        int tj1 = (wi+1 >= 0) ? own[wi + 1] : h[wi + 9];
                        int tj2 = (wi+2 >= 0) ? own[wi + 2] : h[wi + 10];
                        if (tj == 258) {
                            int a = ((tj1 | (tj2 << 8)) + off) & 4095;
                            m |= (1ull << (a & 15))
                               | (1ull << (16 + ((a >> 4) & 15)))
                               | (1ull << (32 + ((a >> 8) & 15)));
                        }
                    }
                }
                smask[mbase + i] = (u32)(m >> shift);
            }
        }
    }
    __syncthreads();

    // ---- store phase: LDS gather -> STG.128 stream (default write-back) ----
    int l = tid & 7;                 // float4 lane within slice
    int g = tid >> 3;                // token group 0..63
    int glane = sl * 8 + l;
    float4* outp = out4 + (size_t)(tokbase + g) * 128 + glane;

    if (sl == 6) {
#pragma unroll 8
        for (int k = 0; k < TOKC / 64; k++) {
            int tt = g + 64 * k;
            float4 v = stbl[(int)stok[tt] * 8 + l];
            u32 mw = smask[tt];
            float* vp = (float*)&v;
#pragma unroll
            for (int c = 0; c < 4; c++) {
                int bi = 4 * l + c - 14;          // dim = 192+4l+c, bit = dim-206
                if (bi >= 0 && ((mw >> bi) & 1u)) vp[c] = 1.0f;
            }
            outp[(size_t)(64 * k) * 128] = v;
        }
    } else if (sl == 7) {
#pragma unroll 8
        for (int k = 0; k < TOKC / 64; k++) {
            int tt = g + 64 * k;
            float4 v = stbl[(int)stok[tt] * 8 + l];
            u32 mw = smask[tt];
            float* vp = (float*)&v;
#pragma unroll
            for (int c = 0; c < 4; c++) {
                int bi = 4 * l + c;               // dim = 224+4l+c, bit = dim-206-18
                if (bi < 30 && ((mw >> bi) & 1u)) vp[c] = 1.0f;
            }
            outp[(size_t)(64 * k) * 128] = v;
        }
    } else if (sl == 14) {
#pragma unroll 8
        for (int k = 0; k < TOKC / 64; k++) {
            int tt = g + 64 * k;
            int t = (int)stok[tt];
            float4 v = stbl[t * 8 + l];
            if (l == 2) {                          // dims 456..459
                int srel = (tokbase + tt) & (SS - 1);
                if (t == 259) v.x = 1.0f;                     // 456
                if (t == 260) v.y = 1.0f;                     // 457
                if (t == 258 && srel < SS - 8) v.z = 1.0f;    // 458
            }
            outp[(size_t)(64 * k) * 128] = v;
        }
    } else {
#pragma unroll 8
        for (int k = 0; k < TOKC / 64; k++) {
            int tt = g + 64 * k;
            float4 v = stbl[(int)stok[tt] * 8 + l];
            outp[(size_t)(64 * k) * 128] = v;
        }
    }
}

// ---------------------------------------------------------------------------
extern "C" void kernel_launch(void* const* d_in, const int* in_sizes, int n_in,
                              void* d_out, int out_size) {
    const float* tbl;
    const int* tok;
    if (in_sizes[0] == 272 * 512) {
        tbl = (const float*)d_in[0];
        tok = (const int*)d_in[1];
    } else {
        tbl = (const float*)d_in[1];
        tok = (const int*)d_in[0];
    }
    float* out = (float*)d_out;

    cudaFuncSetAttribute(nvm_fused_kernel,
                         cudaFuncAttributeMaxDynamicSharedMemorySize,
                         SMEM_BYTES);

    dim3 grid(NCH, SLICES);   // (32, 16) = 512 blocks
    nvm_fused_kernel<<<grid, 512, SMEM_BYTES>>>(
        (const float4*)tbl, tok, (float4*)out);
}

// round 15
// speedup vs baseline: 1.0789x; 1.0789x over previous
#include <cuda_runtime.h>
#include <cstdint>

// FINAL (session best, verified 4x): single fused launch, at the HBM-write
// roofline. 134 MB mandatory output / ~22.7 us kernel = ~5.9 TB/s sustained
// write bandwidth (~74% of 8 TB/s spec). Dim-sliced SMEM-resident table;
// only slices 6/7 run the row scan; slice 14 handles flag dims; __stcs
// evict-first stores (best of stcs/default/wt/bulk A-Bs).

#define BB 8
#define SS 8192
#define NTOK (BB * SS)
#define TOKC 2048
#define NCH (NTOK / TOKC)      // 32 token chunks
#define SLICES 16

typedef unsigned long long u64;
typedef unsigned int u32;
typedef unsigned short u16;

// dynamic smem layout (bytes):
//   [0,      34816)  float4 stbl[272*8]   table slice (32 dims)
//   [34816,  38912)  u16   stok[2048]     chunk tokens
//   [38912,  47104)  u32   smask[2048]    per-token mask slice (sl 6/7 only)
//   [47104,  47168)  int   warp_part[16]
//   [47168,  47232)  int   warp_min[16]
//   [47232,  47236)  int   s_fce
#define SMEM_BYTES 47296

__global__ void __launch_bounds__(512, 3) nvm_fused_kernel(
    const float4* __restrict__ tbl4,     // [272 * 128]
    const int*    __restrict__ tok,      // [NTOK]
    float4*       __restrict__ out4)     // [NTOK * 128]
{
    extern __shared__ char smem[];
    float4* stbl      = (float4*)(smem);
    u16*    stok      = (u16*)(smem + 34816);
    u32*    smask     = (u32*)(smem + 38912);
    int*    warp_part = (int*)(smem + 47104);
    int*    warp_min  = (int*)(smem + 47168);
    int*    s_fce     = (int*)(smem + 47232);

    int sl      = blockIdx.y;            // 0..15 dim slice
    int tokbase = blockIdx.x * TOKC;
    int b       = tokbase >> 13;         // batch row
    int ci      = (tokbase >> 11) & 3;   // chunk within row (0..3)
    int tid     = threadIdx.x;
    int lane    = tid & 31, wid = tid >> 5;

    // ---- stage table slice (272 rows x 8 float4) ----
#pragma unroll
    for (int i = tid; i < 272 * 8; i += 512)
        stbl[i] = __ldg(&tbl4[(i >> 3) * 128 + sl * 8 + (i & 7)]);

    // ---- stage chunk tokens as u16 ----
    {
        const int4* tok4 = (const int4*)(tok + tokbase);
        u32* st32 = (u32*)stok;
#pragma unroll
        for (int i = tid; i < TOKC / 4; i += 512) {
            int4 v = __ldg(&tok4[i]);
            st32[2 * i]     = (u32)v.x | ((u32)v.y << 16);
            st32[2 * i + 1] = (u32)v.z | ((u32)v.w << 16);
        }
    }

    // ---- slices 6/7: full-row scan + mask build into smem ----
    if (sl == 6 || sl == 7) {
        const int4* row4 = (const int4*)(tok + b * SS);
        int base = tid * 16;                 // row-relative start

        int own[16];
        {
            int4 v0 = __ldg(&row4[tid * 4 + 0]);
            int4 v1 = __ldg(&row4[tid * 4 + 1]);
            int4 v2 = __ldg(&row4[tid * 4 + 2]);
            int4 v3 = __ldg(&row4[tid * 4 + 3]);
            own[0]=v0.x; own[1]=v0.y; own[2]=v0.z; own[3]=v0.w;
            own[4]=v1.x; own[5]=v1.y; own[6]=v1.z; own[7]=v1.w;
            own[8]=v2.x; own[9]=v2.y; own[10]=v2.z; own[11]=v2.w;
            own[12]=v3.x; own[13]=v3.y; own[14]=v3.z; own[15]=v3.w;
        }

        int run = -1, lce = SS;
#pragma unroll
        for (int i = 0; i < 16; i++) {
            int t = own[i];
            if (t == 256) run = base + i;
            if (t == 257 && (base + i) < lce) lce = base + i;
        }
        int e = lce;
#pragma unroll
        for (int off = 16; off > 0; off >>= 1) {
            int o = __shfl_down_sync(0xffffffffu, e, off);
            if (o < e) e = o;
        }
        int v = run;
#pragma unroll
        for (int off = 1; off < 32; off <<= 1) {
            int o = __shfl_up_sync(0xffffffffu, v, off);
            if (lane >= off && o > v) v = o;
        }
        if (lane == 0)  warp_min[wid]  = e;
        if (lane == 31) warp_part[wid] = v;
        __syncthreads();
        if (wid == 0 && lane < 16) {
            int w = warp_part[lane];
#pragma unroll
            for (int off = 1; off < 16; off <<= 1) {
                int o = __shfl_up_sync(0x0000ffffu, w, off);
                if (lane >= off && o > w) w = o;
            }
            warp_part[lane] = w;
            if (lane == 0) {
                int f = SS;
#pragma unroll
                for (int i = 0; i < 16; i++)
                    if (warp_min[i] < f) f = warp_min[i];
                *s_fce = f;
            }
        }
        __syncthreads();

        int wpre = (wid == 0) ? -1 : warp_part[wid - 1];
        int excl = __shfl_up_sync(0xffffffffu, v, 1);
        if (lane == 0) excl = -1;
        int prefix = (excl > wpre) ? excl : wpre;
        int fce = *s_fce;

        // only threads whose 16 tokens lie in this block's chunk build masks
        if ((tid >> 7) == ci) {
            int h[8];
#pragma unroll
            for (int j = 0; j < 8; j++) h[j] = -1;
            if (tid > 0) {
                int4 ha = __ldg(&row4[tid * 4 - 2]);
                int4 hb = __ldg(&row4[tid * 4 - 1]);
                h[0]=ha.x; h[1]=ha.y; h[2]=ha.z; h[3]=ha.w;
                h[4]=hb.x; h[5]=hb.y; h[6]=hb.z; h[7]=hb.w;
            }
            int cur = prefix;
            int shift = (sl == 6) ? 0 : 18;
            int mbase = base - ci * TOKC;        // chunk-relative
#pragma unroll
            for (int i = 0; i < 16; i++) {
                int s = base + i;
                int t = own[i];
                if (t == 256) cur = s;           // inclusive cummax
                u64 m = 0ull;
                // code path
                if (cur >= 0 && s < fce && t < 256) {
                    int seq = s - cur - 1;
                    int bo  = seq & 7;
                    if (seq >= 0 && bo < 5) {
                        int addr = ((seq & ~7) + 2 + bo) & 4095;
                        m |= (1ull << (addr & 15))
                           | (1ull << (16 + ((addr >> 4) & 15)))
                           | (1ull << (32 + ((addr >> 8) & 15)));
                    }
                }
                // mem look-back: j = s-5-off, window idx wi = i-5-off in [-8,10]
#pragma unroll
                for (int off = 0; off < 4; off++) {
                    int jg = s - 5 - off;
                    if (jg >= 0 && (jg + 8) < SS) {
                        const int wi = i - 5 - off;
                        int tj  = (wi   >= 0) ? own[wi]     : h[wi + 8];
                        int tj1 = (wi+1 >= 0) ? own[wi + 1] : h[wi + 9];
                        int tj2 = (wi+2 >= 0) ? own[wi + 2] : h[wi + 10];
                        if (tj == 258) {
                            int a = ((tj1 | (tj2 << 8)) + off) & 4095;
                            m |= (1ull << (a & 15))
                               | (1ull << (16 + ((a >> 4) & 15)))
                               | (1ull << (32 + ((a >> 8) & 15)));
                        }
                    }
                }
                smask[mbase + i] = (u32)(m >> shift);
            }
        }
    }
    __syncthreads();

    // ---- store phase: LDS gather -> STG.128 stream ----
    int l = tid & 7;                 // float4 lane within slice
    int g = tid >> 3;                // token group 0..63
    int glane = sl * 8 + l;
    float4* outp = out4 + (size_t)(tokbase + g) * 128 + glane;

    if (sl == 6) {
#pragma unroll 8
        for (int k = 0; k < TOKC / 64; k++) {
            int tt = g + 64 * k;
            float4 v = stbl[(int)stok[tt] * 8 + l];
            u32 mw = smask[tt];
            float* vp = (float*)&v;
#pragma unroll
            for (int c = 0; c < 4; c++) {
                int bi = 4 * l + c - 14;          // dim = 192+4l+c, bit = dim-206
                if (bi >= 0 && ((mw >> bi) & 1u)) vp[c] = 1.0f;
            }
            __stcs(outp + (size_t)(64 * k) * 128, v);
        }
    } else if (sl == 7) {
#pragma unroll 8
        for (int k = 0; k < TOKC / 64; k++) {
            int tt = g + 64 * k;
            float4 v = stbl[(int)stok[tt] * 8 + l];
            u32 mw = smask[tt];
            float* vp = (float*)&v;
#pragma unroll
            for (int c = 0; c < 4; c++) {
                int bi = 4 * l + c;               // dim = 224+4l+c, bit = dim-206-18
                if (bi < 30 && ((mw >> bi) & 1u)) vp[c] = 1.0f;
            }
            __stcs(outp + (size_t)(64 * k) * 128, v);
        }
    } else if (sl == 14) {
#pragma unroll 8
        for (int k = 0; k < TOKC / 64; k++) {
            int tt = g + 64 * k;
            int t = (int)stok[tt];
            float4 v = stbl[t * 8 + l];
            if (l == 2) {                          // dims 456..459
                int srel = (tokbase + tt) & (SS - 1);
                if (t == 259) v.x = 1.0f;                     // 456
                if (t == 260) v.y = 1.0f;                     // 457
                if (t == 258 && srel < SS - 8) v.z = 1.0f;    // 458
            }
            __stcs(outp + (size_t)(64 * k) * 128, v);
        }
    } else {
#pragma unroll 8
        for (int k = 0; k < TOKC / 64; k++) {
            int tt = g + 64 * k;
            float4 v = stbl[(int)stok[tt] * 8 + l];
            __stcs(outp + (size_t)(64 * k) * 128, v);
        }
    }
}

// ---------------------------------------------------------------------------
extern "C" void kernel_launch(void* const* d_in, const int* in_sizes, int n_in,
                              void* d_out, int out_size) {
    const float* tbl;
    const int* tok;
    if (in_sizes[0] == 272 * 512) {
        tbl = (const float*)d_in[0];
        tok = (const int*)d_in[1];
    } else {
        tbl = (const float*)d_in[1];
        tok = (const int*)d_in[0];
    }
    float* out = (float*)d_out;

    cudaFuncSetAttribute(nvm_fused_kernel,
                         cudaFuncAttributeMaxDynamicSharedMemorySize,
                         SMEM_BYTES);

    dim3 grid(NCH, SLICES);   // (32, 16) = 512 blocks
    nvm_fused_kernel<<<grid, 512, SMEM_BYTES>>>(
        (const float4*)tbl, tok, (float4*)out);
}